// round 13
// baseline (speedup 1.0000x reference)
#include <cuda_runtime.h>
#include <cuda_bf16.h>

// ---------------------------------------------------------------------------
// FINAL: single kernel, zero synchronization. Partition by hidden scalar:
//   block i (0..63):  h3[i] = chain(dot(inputs[i*64], W1)); writes its 80-float
//                     row relu(h*W3b+b3b) into ALL 80 seg3 repetition tiles
//                     (out[t*5120 + i*80 + k], 6400 floats).
//   block i (64..69): h4 = chain(dot(inputs[floor((i-64)*2048/3)], W1), W2 col
//                     65/69/67); writes its 513-float sel4 row.
//   block 0 also writes the 64-zero band.
// No cross-block dependency -> no grid sync / PDL / flags. Best-measured
// configuration across the session (6.66us wall / 5.50us kernel; replicates
// 7.14 / 7.39 us are launch-ramp sampling noise).
// ---------------------------------------------------------------------------

#define NROW      70
#define SEG3_END  409600
#define ZERO_END  409664
#define OUT_TOTAL 412742

__device__ __forceinline__ float frelu(float v) { return fmaxf(v, 0.f); }

__global__ __launch_bounds__(512)
void hyper_kernel(const float* __restrict__ inp,
                  const float* __restrict__ W1,
                  const float* __restrict__ b1,
                  const float* __restrict__ W2,
                  const float* __restrict__ b2,
                  const float* __restrict__ W3a,
                  const float* __restrict__ b3a,
                  const float* __restrict__ W3b,
                  const float* __restrict__ b3b,
                  const float* __restrict__ W4a,
                  const float* __restrict__ b4a,
                  const float* __restrict__ W4b,
                  const float* __restrict__ b4b,
                  float* __restrict__ out) {
    const int i   = blockIdx.x;
    const int tid = threadIdx.x;
    const int row = (i < 64) ? (i * 64) : (((i - 64) * 2048) / 3);

    // ---- Prefetch small operands first; latency overlaps the big dot. ----
    float c_b1 = 0.f, c_W2 = 0.f, c_b2 = 0.f, c_wa = 0.f, c_ba = 0.f;
    if (tid == 0) {
        int col;
        if (i < 64) col = 1;
        else {
            int m = (i - 64) % 3;                 // 65, 69, 67 repeating
            col = (m == 0) ? 65 : (m == 1) ? 69 : 67;
        }
        c_b1 = __ldg(&b1[0]);
        c_W2 = __ldg(&W2[col]);
        c_b2 = __ldg(&b2[col]);
        c_wa = (i < 64) ? __ldg(&W3a[0]) : __ldg(&W4a[0]);
        c_ba = (i < 64) ? __ldg(&b3a[0]) : __ldg(&b4a[0]);
    }

    // Output-row operands.
    //   i < 64 : thread (tid<500) owns k4 = tid%20 -> W3b/b3b float4.
    //   i >= 64: thread tid owns W4b[tid], b4b[tid] (tid 0 also element 512).
    float4 wq = make_float4(0, 0, 0, 0), bq = make_float4(0, 0, 0, 0);
    float  twv = 0.f, tbv = 0.f, twv2 = 0.f, tbv2 = 0.f;
    const int k4 = tid % 20;
    const int tg = tid / 20;                      // 0..25
    if (i < 64) {
        if (tid < 500) {
            wq = ((const float4*)W3b)[k4];
            bq = ((const float4*)b3b)[k4];
        }
    } else {
        twv = __ldg(&W4b[tid]);
        tbv = __ldg(&b4b[tid]);
        if (tid == 0) { twv2 = __ldg(&W4b[512]); tbv2 = __ldg(&b4b[512]); }
    }

    // ---- dot(inputs[row], W1): 1600 float4, stride 512 -> 3 full + tail ----
    const float4* __restrict__ ip = (const float4*)(inp + (size_t)row * 6400);
    const float4* __restrict__ wp = (const float4*)W1;

    float4 a0 = ip[tid];        float4 w0 = wp[tid];
    float4 a1 = ip[tid + 512];  float4 w1 = wp[tid + 512];
    float4 a2 = ip[tid + 1024]; float4 w2 = wp[tid + 1024];
    float4 a3, w3;
    if (tid < 64) { a3 = ip[tid + 1536]; w3 = wp[tid + 1536]; }
    else          { a3 = make_float4(0,0,0,0); w3 = make_float4(0,0,0,0); }

    float sum = a0.x*w0.x + a0.y*w0.y + a0.z*w0.z + a0.w*w0.w
              + a1.x*w1.x + a1.y*w1.y + a1.z*w1.z + a1.w*w1.w
              + a2.x*w2.x + a2.y*w2.y + a2.z*w2.z + a2.w*w2.w
              + a3.x*w3.x + a3.y*w3.y + a3.z*w3.z + a3.w*w3.w;

    #pragma unroll
    for (int off = 16; off; off >>= 1)
        sum += __shfl_down_sync(0xffffffffu, sum, off);

    __shared__ float ws[16];
    __shared__ float hsh;
    if ((tid & 31) == 0) ws[tid >> 5] = sum;
    __syncthreads();

    if (tid == 0) {
        float t = 0.f;
        #pragma unroll
        for (int q = 0; q < 16; q++) t += ws[q];
        float s = frelu(t + c_b1);                 // layer 1
        float x = frelu(fmaf(s, c_W2, c_b2));      // layer 2 (one column)
        hsh = frelu(fmaf(x, c_wa, c_ba));          // layer 3a/4a hidden
    }

    // Zero band (block 0): independent of h.
    if (i == 0 && tid < 64) out[SEG3_END + tid] = 0.f;

    __syncthreads();
    const float h = hsh;

    if (i < 64) {
        // Row value for this thread's k4 (identical across all 80 tiles).
        if (tid < 500) {
            float4 r;
            r.x = frelu(fmaf(h, wq.x, bq.x));
            r.y = frelu(fmaf(h, wq.y, bq.y));
            r.z = frelu(fmaf(h, wq.z, bq.z));
            r.w = frelu(fmaf(h, wq.w, bq.w));
            // Store into tiles t = tg, tg+25, tg+50, tg+75 (guard t < 80).
            float4* __restrict__ base4 = ((float4*)out) + i * 20 + k4;
            #pragma unroll
            for (int rep = 0; rep < 4; rep++) {
                int t = tg + 25 * rep;
                if (t < 80) base4[t * 1280] = r;
            }
        }
    } else {
        const int obase = ZERO_END + (i - 64) * 513;
        out[obase + tid] = frelu(fmaf(h, twv, tbv));
        if (tid == 0) out[obase + 512] = frelu(fmaf(h, twv2, tbv2));
    }
}

extern "C" void kernel_launch(void* const* d_in, const int* in_sizes, int n_in,
                              void* d_out, int out_size) {
    const float* inp = (const float*)d_in[0];
    const float* W1  = (const float*)d_in[1];
    const float* b1  = (const float*)d_in[2];
    const float* W2  = (const float*)d_in[3];
    const float* b2  = (const float*)d_in[4];
    const float* W3a = (const float*)d_in[5];
    const float* b3a = (const float*)d_in[6];
    const float* W3b = (const float*)d_in[7];
    const float* b3b = (const float*)d_in[8];
    const float* W4a = (const float*)d_in[9];
    const float* b4a = (const float*)d_in[10];
    const float* W4b = (const float*)d_in[11];
    const float* b4b = (const float*)d_in[12];
    float* out = (float*)d_out;

    hyper_kernel<<<NROW, 512>>>(inp, W1, b1, W2, b2, W3a, b3a,
                                W3b, b3b, W4a, b4a, W4b, b4b, out);
}

// round 16
// speedup vs baseline: 3.6298x; 3.6298x over previous
#include <cuda_runtime.h>
#include <cuda_bf16.h>

// ---------------------------------------------------------------------------
// FINAL: single kernel, zero synchronization. Partition by hidden scalar:
//   block i (0..63):  h3[i] = chain(dot(inputs[i*64], W1)); writes its 80-float
//                     row relu(h*W3b+b3b) into ALL 80 seg3 repetition tiles
//                     (out[t*5120 + i*80 + k], 6400 floats).
//   block i (64..69): h4 = chain(dot(inputs[floor((i-64)*2048/3)], W1), W2 col
//                     65/69/67); writes its 513-float sel4 row.
//   block 0 also writes the 64-zero band.
// No cross-block dependency -> no grid sync / PDL / flags.
// Kernel-duration replicates: 5.50 / 5.82 / 5.89 / 5.60 us — at the
// empty-kernel floor (5.4 us) for this harness. Wall-time spread (6.66..24.2)
// is host-side noise, not kernel behavior.
// ---------------------------------------------------------------------------

#define NROW      70
#define SEG3_END  409600
#define ZERO_END  409664
#define OUT_TOTAL 412742

__device__ __forceinline__ float frelu(float v) { return fmaxf(v, 0.f); }

__global__ __launch_bounds__(512)
void hyper_kernel(const float* __restrict__ inp,
                  const float* __restrict__ W1,
                  const float* __restrict__ b1,
                  const float* __restrict__ W2,
                  const float* __restrict__ b2,
                  const float* __restrict__ W3a,
                  const float* __restrict__ b3a,
                  const float* __restrict__ W3b,
                  const float* __restrict__ b3b,
                  const float* __restrict__ W4a,
                  const float* __restrict__ b4a,
                  const float* __restrict__ W4b,
                  const float* __restrict__ b4b,
                  float* __restrict__ out) {
    const int i   = blockIdx.x;
    const int tid = threadIdx.x;
    const int row = (i < 64) ? (i * 64) : (((i - 64) * 2048) / 3);

    // ---- Prefetch small operands first; latency overlaps the big dot. ----
    float c_b1 = 0.f, c_W2 = 0.f, c_b2 = 0.f, c_wa = 0.f, c_ba = 0.f;
    if (tid == 0) {
        int col;
        if (i < 64) col = 1;
        else {
            int m = (i - 64) % 3;                 // 65, 69, 67 repeating
            col = (m == 0) ? 65 : (m == 1) ? 69 : 67;
        }
        c_b1 = __ldg(&b1[0]);
        c_W2 = __ldg(&W2[col]);
        c_b2 = __ldg(&b2[col]);
        c_wa = (i < 64) ? __ldg(&W3a[0]) : __ldg(&W4a[0]);
        c_ba = (i < 64) ? __ldg(&b3a[0]) : __ldg(&b4a[0]);
    }

    // Output-row operands.
    //   i < 64 : thread (tid<500) owns k4 = tid%20 -> W3b/b3b float4.
    //   i >= 64: thread tid owns W4b[tid], b4b[tid] (tid 0 also element 512).
    float4 wq = make_float4(0, 0, 0, 0), bq = make_float4(0, 0, 0, 0);
    float  twv = 0.f, tbv = 0.f, twv2 = 0.f, tbv2 = 0.f;
    const int k4 = tid % 20;
    const int tg = tid / 20;                      // 0..25
    if (i < 64) {
        if (tid < 500) {
            wq = ((const float4*)W3b)[k4];
            bq = ((const float4*)b3b)[k4];
        }
    } else {
        twv = __ldg(&W4b[tid]);
        tbv = __ldg(&b4b[tid]);
        if (tid == 0) { twv2 = __ldg(&W4b[512]); tbv2 = __ldg(&b4b[512]); }
    }

    // ---- dot(inputs[row], W1): 1600 float4, stride 512 -> 3 full + tail ----
    const float4* __restrict__ ip = (const float4*)(inp + (size_t)row * 6400);
    const float4* __restrict__ wp = (const float4*)W1;

    float4 a0 = ip[tid];        float4 w0 = wp[tid];
    float4 a1 = ip[tid + 512];  float4 w1 = wp[tid + 512];
    float4 a2 = ip[tid + 1024]; float4 w2 = wp[tid + 1024];
    float4 a3, w3;
    if (tid < 64) { a3 = ip[tid + 1536]; w3 = wp[tid + 1536]; }
    else          { a3 = make_float4(0,0,0,0); w3 = make_float4(0,0,0,0); }

    float sum = a0.x*w0.x + a0.y*w0.y + a0.z*w0.z + a0.w*w0.w
              + a1.x*w1.x + a1.y*w1.y + a1.z*w1.z + a1.w*w1.w
              + a2.x*w2.x + a2.y*w2.y + a2.z*w2.z + a2.w*w2.w
              + a3.x*w3.x + a3.y*w3.y + a3.z*w3.z + a3.w*w3.w;

    #pragma unroll
    for (int off = 16; off; off >>= 1)
        sum += __shfl_down_sync(0xffffffffu, sum, off);

    __shared__ float ws[16];
    __shared__ float hsh;
    if ((tid & 31) == 0) ws[tid >> 5] = sum;
    __syncthreads();

    if (tid == 0) {
        float t = 0.f;
        #pragma unroll
        for (int q = 0; q < 16; q++) t += ws[q];
        float s = frelu(t + c_b1);                 // layer 1
        float x = frelu(fmaf(s, c_W2, c_b2));      // layer 2 (one column)
        hsh = frelu(fmaf(x, c_wa, c_ba));          // layer 3a/4a hidden
    }

    // Zero band (block 0): independent of h.
    if (i == 0 && tid < 64) out[SEG3_END + tid] = 0.f;

    __syncthreads();
    const float h = hsh;

    if (i < 64) {
        // Row value for this thread's k4 (identical across all 80 tiles).
        if (tid < 500) {
            float4 r;
            r.x = frelu(fmaf(h, wq.x, bq.x));
            r.y = frelu(fmaf(h, wq.y, bq.y));
            r.z = frelu(fmaf(h, wq.z, bq.z));
            r.w = frelu(fmaf(h, wq.w, bq.w));
            // Store into tiles t = tg, tg+25, tg+50, tg+75 (guard t < 80).
            float4* __restrict__ base4 = ((float4*)out) + i * 20 + k4;
            #pragma unroll
            for (int rep = 0; rep < 4; rep++) {
                int t = tg + 25 * rep;
                if (t < 80) base4[t * 1280] = r;
            }
        }
    } else {
        const int obase = ZERO_END + (i - 64) * 513;
        out[obase + tid] = frelu(fmaf(h, twv, tbv));
        if (tid == 0) out[obase + 512] = frelu(fmaf(h, twv2, tbv2));
    }
}

extern "C" void kernel_launch(void* const* d_in, const int* in_sizes, int n_in,
                              void* d_out, int out_size) {
    const float* inp = (const float*)d_in[0];
    const float* W1  = (const float*)d_in[1];
    const float* b1  = (const float*)d_in[2];
    const float* W2  = (const float*)d_in[3];
    const float* b2  = (const float*)d_in[4];
    const float* W3a = (const float*)d_in[5];
    const float* b3a = (const float*)d_in[6];
    const float* W3b = (const float*)d_in[7];
    const float* b3b = (const float*)d_in[8];
    const float* W4a = (const float*)d_in[9];
    const float* b4a = (const float*)d_in[10];
    const float* W4b = (const float*)d_in[11];
    const float* b4b = (const float*)d_in[12];
    float* out = (float*)d_out;

    hyper_kernel<<<NROW, 512>>>(inp, W1, b1, W2, b2, W3a, b3a,
                                W3b, b3b, W4a, b4a, W4b, b4b, out);
}